// round 12
// baseline (speedup 1.0000x reference)
#include <cuda_runtime.h>
#include <cuda_bf16.h>
#include <math.h>

// LF-MMI loss: CTC numerator (log domain) + dense bigram denominator forward.
// Denominator: linear-domain scaled forward, 2-CTA cluster per batch element,
//   column-split. g0 (tid<128) computes own-half rows + combines/sends; g1
//   computes peer-half rows, paced by the alpha mbarrier. Texp slice in
//   registers, fma.rn.f32x2. Exchange: per-thread st.async, per-buffer
//   mbarriers. Renorm every 32 steps g0-only.
// Numerator: log-domain CTC forward.
// SINGLE LAUNCH: finalize fused via last-block atomic counter (also makes
//   ncu's Nth-launch sampling hit this kernel deterministically).

#define CC 256
#define NEGBIG (-1.0e30f)

__device__ float g_num[512];
__device__ float g_den[512];
__device__ unsigned int g_done = 0;

// den smem byte offsets (dynamic smem)
#define OFF_MBAR   0     // 2 x 8B alpha mbarriers (one per buffer)
#define OFF_SMBAR  16    // 2 x 8B scalar mbarriers (renorm)
#define OFF_SSLOT  32    // 2 x 4B peer half-sum slots (+pad)
#define OFF_ASH    48    // 128 floats: my alpha half
#define OFF_PIN    560   // 2 x 128 floats: peer alpha half (double buffered)
#define OFF_PART   1584  // 2 x 128 floats: g1 partials (double buffered)
#define OFF_RED    2608  // 8 floats
#define OFF_TMP    2640  // 256 floats init scratch
#define DEN_SMEM   3664

__device__ __forceinline__ float blk_sum_256(float v, float* red) {
    int tid = threadIdx.x;
#pragma unroll
    for (int o = 16; o > 0; o >>= 1) v += __shfl_xor_sync(0xffffffffu, v, o);
    if ((tid & 31) == 0) red[tid >> 5] = v;
    __syncthreads();
    float s = red[0] + red[1] + red[2] + red[3] + red[4] + red[5] + red[6] + red[7];
    __syncthreads();
    return s;
}

__device__ __forceinline__ unsigned long long pack2(float lo, float hi) {
    unsigned long long r;
    asm("mov.b64 %0, {%1, %2};" : "=l"(r) : "r"(__float_as_uint(lo)), "r"(__float_as_uint(hi)));
    return r;
}

__device__ __forceinline__ void mbar_wait_parity(unsigned int mbar, unsigned int parity) {
    asm volatile(
        "{\n\t"
        ".reg .pred P;\n\t"
        "WL_%=:\n\t"
        "mbarrier.try_wait.parity.acquire.cluster.shared::cta.b64 P, [%0], %1, 0x989680;\n\t"
        "@P bra.uni WD_%=;\n\t"
        "bra.uni WL_%=;\n\t"
        "WD_%=:\n\t"
        "}" :: "r"(mbar), "r"(parity) : "memory");
}

__device__ __forceinline__ void bar_g0() {   // g0-only barrier (128 threads)
    asm volatile("bar.sync 1, 128;" ::: "memory");
}

// ---------------------------------------------------------------------------
// Denominator: cluster of 2 CTAs per batch element. 256 threads each.
// ---------------------------------------------------------------------------
__device__ void den_block(unsigned char* smem_raw,
                          const float* __restrict__ logp,
                          const int* __restrict__ in_len_raw,
                          const float* __restrict__ trans,
                          const float* __restrict__ start,
                          int b, int h, int T, int U) {
    int tid = threadIdx.x;
    int g   = tid >> 7;       // 0: own-half rows + combine/send; 1: peer-half rows
    int j   = tid & 127;      // column within my half
    int gcol = h * 128 + j;   // global output column

    unsigned int sbase;
    asm("{ .reg .u64 t; cvta.to.shared.u64 t, %1; cvt.u32.u64 %0, t; }"
        : "=r"(sbase) : "l"(smem_raw));
    unsigned int mbar_l  = sbase + OFF_MBAR;
    unsigned int smbar_l = sbase + OFF_SMBAR;

    float* a_sh   = (float*)(smem_raw + OFF_ASH);
    float* p_in   = (float*)(smem_raw + OFF_PIN);
    float* part   = (float*)(smem_raw + OFF_PART);
    float* red    = (float*)(smem_raw + OFF_RED);
    float* tmp    = (float*)(smem_raw + OFF_TMP);
    float* s_slot = (float*)(smem_raw + OFF_SSLOT);

    int peer = h ^ 1;
    unsigned int mbar_p, smbar_p, pin_p, sslot_p;
    asm("mapa.shared::cluster.u32 %0, %1, %2;" : "=r"(mbar_p)  : "r"(mbar_l), "r"(peer));
    asm("mapa.shared::cluster.u32 %0, %1, %2;" : "=r"(smbar_p) : "r"(smbar_l), "r"(peer));
    asm("mapa.shared::cluster.u32 %0, %1, %2;" : "=r"(pin_p)   : "r"(sbase + OFF_PIN), "r"(peer));
    asm("mapa.shared::cluster.u32 %0, %1, %2;" : "=r"(sslot_p) : "r"(sbase + OFF_SSLOT), "r"(peer));

    if (tid == 0) {
        asm volatile("mbarrier.init.shared.b64 [%0], %1;" :: "r"(mbar_l),      "r"(1) : "memory");
        asm volatile("mbarrier.init.shared.b64 [%0], %1;" :: "r"(mbar_l + 8),  "r"(1) : "memory");
        asm volatile("mbarrier.init.shared.b64 [%0], %1;" :: "r"(smbar_l),     "r"(1) : "memory");
        asm volatile("mbarrier.init.shared.b64 [%0], %1;" :: "r"(smbar_l + 8), "r"(1) : "memory");
    }

    // T column slice in registers: rows [(h^g)*128, +128) for column gcol.
    unsigned long long Treg[64];
    const float* trow = trans + (size_t)((h ^ g) * 128) * CC + gcol;
#pragma unroll
    for (int rp = 0; rp < 64; rp++) {
        float e0 = __expf(trow[(2 * rp) * CC]);
        float e1 = __expf(trow[(2 * rp + 1) * CC]);
        Treg[rp] = pack2(e0, e1);
    }

    int inlen = in_len_raw[b];
    int lowc = 2 * U + 1;
    if (inlen < lowc) inlen = lowc;
    if (inlen > T)    inlen = T;

    const float* lpb = logp + (size_t)b * T * CC;

    // alpha0 = exp(start + logp[:,0]) normalized; seed a_sh (my half) and
    // p_in[0] (peer half, computed locally -- no exchange needed for t=1).
    float a0 = __expf(start[tid] + lpb[tid]);
    tmp[tid] = a0;
    __syncthreads();
    float s0 = blk_sum_256(a0, red);
    float logZ = logf(s0);
    float inv0 = 1.0f / s0;
    if (tid < 128) {
        a_sh[tid]     = tmp[h * 128 + tid] * inv0;
        p_in[0 + tid] = tmp[peer * 128 + tid] * inv0;
    }
    float lp_reg = (g == 0) ? lpb[CC + gcol] : 0.0f;   // frame t=1 for my col
    __syncthreads();

    asm volatile("barrier.cluster.arrive.aligned;" ::: "memory");
    asm volatile("barrier.cluster.wait.aligned;" ::: "memory");

    const longlong2* own2 = (const longlong2*)a_sh;
    int ph0 = 0, ph1 = 0;   // per-buffer phase parity trackers (g1)
    int rc = 0;             // renorm counter (g0)

    if (g == 0) {
        // ------------------------- g0 loop -------------------------
        for (int t = 1; t < inlen; ++t) {
            int buf = t & 1;
            if (tid == 0) {   // arm for incoming peer alpha(t): 128 floats
                asm volatile("mbarrier.arrive.expect_tx.shared.b64 _, [%0], %1;"
                             :: "r"(mbar_l + (unsigned)buf * 8u), "r"(512) : "memory");
            }
            // issue exp + next-frame prefetch EARLY: overlap with FMA phase
            float pv = __expf(lp_reg);
            if (t + 1 < inlen) lp_reg = lpb[(size_t)(t + 1) * CC + gcol];

            unsigned long long acc0 = 0ull, acc1 = 0ull, acc2 = 0ull, acc3 = 0ull;
#pragma unroll
            for (int i = 0; i < 16; i++) {
                longlong2 x = own2[2 * i];
                longlong2 y = own2[2 * i + 1];
                asm("fma.rn.f32x2 %0, %1, %2, %0;" : "+l"(acc0) : "l"((unsigned long long)x.x), "l"(Treg[4 * i + 0]));
                asm("fma.rn.f32x2 %0, %1, %2, %0;" : "+l"(acc1) : "l"((unsigned long long)x.y), "l"(Treg[4 * i + 1]));
                asm("fma.rn.f32x2 %0, %1, %2, %0;" : "+l"(acc2) : "l"((unsigned long long)y.x), "l"(Treg[4 * i + 2]));
                asm("fma.rn.f32x2 %0, %1, %2, %0;" : "+l"(acc3) : "l"((unsigned long long)y.y), "l"(Treg[4 * i + 3]));
            }
            asm("add.rn.f32x2 %0, %0, %1;" : "+l"(acc0) : "l"(acc1));
            asm("add.rn.f32x2 %0, %0, %1;" : "+l"(acc2) : "l"(acc3));
            asm("add.rn.f32x2 %0, %0, %1;" : "+l"(acc0) : "l"(acc2));
            unsigned int plo, phi;
            asm("mov.b64 {%0, %1}, %2;" : "=r"(plo), "=r"(phi) : "l"(acc0));
            float partial = __uint_as_float(plo) + __uint_as_float(phi);

            __syncthreads();   // bar0: g1's part[buf] ready
            float an = (partial + part[buf * 128 + j]) * pv;

            if (((t & 31) == 31) || (t == inlen - 1)) {
                // g0-only renorm
                float v = an;
#pragma unroll
                for (int o = 16; o > 0; o >>= 1) v += __shfl_xor_sync(0xffffffffu, v, o);
                if ((tid & 31) == 0) red[tid >> 5] = v;
                bar_g0();
                float sl = red[0] + red[1] + red[2] + red[3];
                int bs = rc & 1;
                if (tid == 0) {
                    asm volatile("mbarrier.arrive.expect_tx.shared.b64 _, [%0], %1;"
                                 :: "r"(smbar_l + (unsigned)bs * 8u), "r"(4) : "memory");
                    asm volatile("st.async.shared::cluster.mbarrier::complete_tx::bytes.b32"
                                 " [%0], %1, [%2];"
                                 :: "r"(sslot_p + (unsigned)bs * 4u),
                                    "r"(__float_as_uint(sl)),
                                    "r"(smbar_p + (unsigned)bs * 8u) : "memory");
                }
                mbar_wait_parity(smbar_l + (unsigned)bs * 8u, (unsigned)((rc >> 1) & 1));
                float sp = s_slot[bs];
                float s  = (h == 0) ? (sl + sp) : (sp + sl);
                logZ += logf(s);
                an *= (1.0f / s);
                rc++;
                bar_g0();   // protect red reuse
            }

            a_sh[j] = an;
            asm volatile("st.async.shared::cluster.mbarrier::complete_tx::bytes.b32"
                         " [%0], %1, [%2];"
                         :: "r"(pin_p + (unsigned)buf * 512u + (unsigned)j * 4u),
                            "r"(__float_as_uint(an)),
                            "r"(mbar_p + (unsigned)buf * 8u) : "memory");
            bar_g0();          // a_sh WAR before next phase A (g0-only)
        }
        if (h == 0 && tid == 0) g_den[b] = logZ;
    } else {
        // ------------------------- g1 loop -------------------------
        for (int t = 1; t < inlen; ++t) {
            int buf = t & 1;
            int br  = (t - 1) & 1;
            if (t >= 2) {
                int par = br ? ph1 : ph0;
                mbar_wait_parity(mbar_l + (unsigned)br * 8u, (unsigned)par);
                if (br) ph1 ^= 1; else ph0 ^= 1;
            }
            const longlong2* src2 = (const longlong2*)(p_in + br * 128);
            unsigned long long acc0 = 0ull, acc1 = 0ull, acc2 = 0ull, acc3 = 0ull;
#pragma unroll
            for (int i = 0; i < 16; i++) {
                longlong2 x = src2[2 * i];
                longlong2 y = src2[2 * i + 1];
                asm("fma.rn.f32x2 %0, %1, %2, %0;" : "+l"(acc0) : "l"((unsigned long long)x.x), "l"(Treg[4 * i + 0]));
                asm("fma.rn.f32x2 %0, %1, %2, %0;" : "+l"(acc1) : "l"((unsigned long long)x.y), "l"(Treg[4 * i + 1]));
                asm("fma.rn.f32x2 %0, %1, %2, %0;" : "+l"(acc2) : "l"((unsigned long long)y.x), "l"(Treg[4 * i + 2]));
                asm("fma.rn.f32x2 %0, %1, %2, %0;" : "+l"(acc3) : "l"((unsigned long long)y.y), "l"(Treg[4 * i + 3]));
            }
            asm("add.rn.f32x2 %0, %0, %1;" : "+l"(acc0) : "l"(acc1));
            asm("add.rn.f32x2 %0, %0, %1;" : "+l"(acc2) : "l"(acc3));
            asm("add.rn.f32x2 %0, %0, %1;" : "+l"(acc0) : "l"(acc2));
            unsigned int plo, phi;
            asm("mov.b64 {%0, %1}, %2;" : "=r"(plo), "=r"(phi) : "l"(acc0));
            part[buf * 128 + j] = __uint_as_float(plo) + __uint_as_float(phi);

            __syncthreads();   // bar0: hand part[buf] to g0
        }
    }

    asm volatile("barrier.cluster.arrive.aligned;" ::: "memory");
    asm volatile("barrier.cluster.wait.aligned;" ::: "memory");
}

// ---------------------------------------------------------------------------
// CTC numerator block (LOG domain): one block per batch element. 256 threads.
// ---------------------------------------------------------------------------
__device__ void ctc_block(unsigned char* smem_raw,
                          const float* __restrict__ logp,
                          const int* __restrict__ targets,
                          const int* __restrict__ in_len_raw,
                          const int* __restrict__ tgt_len_raw,
                          int b, int T, int U) {
    int tid = threadIdx.x;
    int S = 2 * U + 1;

    float* A0  = (float*)smem_raw;          // S+6 (2 leading NEG guards)
    float* A1  = A0 + (S + 6);
    int*   lab = (int*)(A1 + (S + 6));      // S
    int*   skp = lab + S;                   // S
    float* pc  = (float*)(skp + S);         // 256

    const int* tg = targets + (size_t)b * U;
    int tlen = tgt_len_raw[b];
    if (tlen < 1) tlen = 1;
    if (tlen > U) tlen = U;
    int inlen = in_len_raw[b];
    int lowc = 2 * U + 1;
    if (inlen < lowc) inlen = lowc;
    if (inlen > T)    inlen = T;

    for (int s = tid; s < S; s += 256) {
        int l = 0;
        if (s & 1) {
            l = tg[s >> 1];
            if (l < 1) l = 1;
            if (l > CC - 1) l = CC - 1;
        }
        lab[s] = l;
    }
    for (int s = tid; s < S + 6; s += 256) { A0[s] = NEGBIG; A1[s] = NEGBIG; }
    __syncthreads();
    for (int s = tid; s < S; s += 256)
        skp[s] = (s >= 2 && (s & 1) && lab[s] != lab[s - 2]) ? 1 : 0;

    const float* lpb = logp + (size_t)b * T * CC;
    if (tid == 0) {
        A0[2 + 0] = lpb[0];
        A0[2 + 1] = lpb[lab[1]];
    }
    pc[tid] = lpb[CC + tid];
    float lp_reg = lpb[2 * (size_t)CC + tid];
    __syncthreads();

    float* cur = A0;
    float* nxt = A1;
    for (int t = 1; t < inlen; ++t) {
        {
            int s = tid;
            float a  = cur[s + 2];
            float a1 = cur[s + 1];
            float a2 = skp[s] ? cur[s] : NEGBIG;
            float m  = fmaxf(fmaxf(a, a1), a2);
            float v  = __expf(a - m) + __expf(a1 - m) + __expf(a2 - m);
            nxt[s + 2] = m + __logf(v) + pc[lab[s]];
        }
        if (tid < S - 256) {
            int s = tid + 256;
            float a  = cur[s + 2];
            float a1 = cur[s + 1];
            float a2 = skp[s] ? cur[s] : NEGBIG;
            float m  = fmaxf(fmaxf(a, a1), a2);
            float v  = __expf(a - m) + __expf(a1 - m) + __expf(a2 - m);
            nxt[s + 2] = m + __logf(v) + pc[lab[s]];
        }
        __syncthreads();
        if (t + 1 < inlen) {
            pc[tid] = lp_reg;
            if (t + 2 < inlen) lp_reg = lpb[(size_t)(t + 2) * CC + tid];
        }
        __syncthreads();
        float* tmp = cur; cur = nxt; nxt = tmp;
    }
    if (tid == 0) {
        int last = 2 * tlen;
        float a  = cur[last + 2];
        float a1 = cur[last + 1];
        float m  = fmaxf(a, a1);
        g_num[b] = m + logf(expf(a - m) + expf(a1 - m));
    }
}

__global__ __launch_bounds__(256, 1) __cluster_dims__(2, 1, 1)
void lfmmi_kernel(const float* __restrict__ logp,
                  const int* __restrict__ targets,
                  const int* __restrict__ in_len_raw,
                  const int* __restrict__ tgt_len_raw,
                  const float* __restrict__ trans,
                  const float* __restrict__ start,
                  float* __restrict__ out,
                  int B, int T, int U) {
    extern __shared__ unsigned char smem_raw[];
    int blk = blockIdx.x;
    if (blk < 2 * B) {
        den_block(smem_raw, logp, in_len_raw, trans, start, blk >> 1, blk & 1, T, U);
    } else if (blk < 3 * B) {
        ctc_block(smem_raw, logp, targets, in_len_raw, tgt_len_raw, blk - 2 * B, T, U);
    }

    // ---- fused finalize: last block to finish reduces g_num/g_den -> out ----
    __syncthreads();
    if (threadIdx.x == 0) {
        __threadfence();
        unsigned int total = gridDim.x;
        unsigned int old = atomicAdd(&g_done, 1u);
        if ((old % total) == total - 1u) {
            __threadfence();
            float tot = 0.f;
            int cnt = 0;
            for (int b = 0; b < B; b++) {
                float v = g_num[b] - g_den[b];
                if (v > 0.5f * NEGBIG) { tot += v; cnt++; }
            }
            int n = (cnt > 0) ? cnt : 1;
            out[0] = -tot / (float)n;
        }
    }
}

extern "C" void kernel_launch(void* const* d_in, const int* in_sizes, int n_in,
                              void* d_out, int out_size) {
    const float* logp   = (const float*)d_in[0];
    const int*   tgts   = (const int*)d_in[1];
    const int*   inl    = (const int*)d_in[2];
    const int*   tgl    = (const int*)d_in[3];
    const float* trans  = (const float*)d_in[4];
    const float* start  = (const float*)d_in[5];

    int B = in_sizes[2];
    int C = in_sizes[5];            // expected 256
    int U = in_sizes[1] / B;
    int T = in_sizes[0] / (B * C);
    int S = 2 * U + 1;

    size_t ctc_smem = (size_t)(2 * (S + 6) + 2 * S + 256 + 16) * 4;
    size_t smem = ctc_smem > DEN_SMEM ? ctc_smem : DEN_SMEM;

    int grid = 3 * B;
    if (grid & 1) grid++;           // cluster size 2 divisibility

    lfmmi_kernel<<<grid, 256, smem>>>(logp, tgts, inl, tgl, trans, start,
                                      (float*)d_out, B, T, U);
}

// round 17
// speedup vs baseline: 1.1760x; 1.1760x over previous
#include <cuda_runtime.h>
#include <cuda_bf16.h>
#include <math.h>

// LF-MMI loss: CTC numerator (log domain) + dense bigram denominator forward.
// Denominator: linear-domain scaled forward, 2-CTA cluster per batch element,
//   column-split. NEW: g1 owns the critical path end-to-end (wait -> peer FMA
//   -> combine -> send); g0 precomputes the own-half dot off-path and the two
//   groups couple through one-directional named barriers (arrive/sync pairs),
//   eliminating both full __syncthreads from the steady-state loop.
//   Texp slice in registers, fma.rn.f32x2. Renorm every 32 steps, g1-side.
// Numerator: log-domain CTC forward.
// Single launch; finalize fused via last-block atomic counter.

#define CC 256
#define NEGBIG (-1.0e30f)

__device__ float g_num[512];
__device__ float g_den[512];
__device__ unsigned int g_done = 0;

// den smem byte offsets (dynamic smem)
#define OFF_MBAR   0     // 2 x 8B alpha mbarriers (one per buffer)
#define OFF_SMBAR  16    // 2 x 8B scalar mbarriers (renorm)
#define OFF_SSLOT  32    // 2 x 4B peer half-sum slots (+pad)
#define OFF_ASH    48    // 128 floats: my alpha half
#define OFF_PIN    560   // 2 x 128 floats: peer alpha half (double buffered)
#define OFF_PART   1584  // 2 x 128 floats: g0 own-dot (double buffered)
#define OFF_RED    2608  // 8 floats
#define OFF_TMP    2640  // 256 floats init scratch
#define DEN_SMEM   3664

__device__ __forceinline__ float blk_sum_256(float v, float* red) {
    int tid = threadIdx.x;
#pragma unroll
    for (int o = 16; o > 0; o >>= 1) v += __shfl_xor_sync(0xffffffffu, v, o);
    if ((tid & 31) == 0) red[tid >> 5] = v;
    __syncthreads();
    float s = red[0] + red[1] + red[2] + red[3] + red[4] + red[5] + red[6] + red[7];
    __syncthreads();
    return s;
}

__device__ __forceinline__ unsigned long long pack2(float lo, float hi) {
    unsigned long long r;
    asm("mov.b64 %0, {%1, %2};" : "=l"(r) : "r"(__float_as_uint(lo)), "r"(__float_as_uint(hi)));
    return r;
}

__device__ __forceinline__ void mbar_wait_parity(unsigned int mbar, unsigned int parity) {
    asm volatile(
        "{\n\t"
        ".reg .pred P;\n\t"
        "WL_%=:\n\t"
        "mbarrier.try_wait.parity.acquire.cluster.shared::cta.b64 P, [%0], %1, 0x989680;\n\t"
        "@P bra.uni WD_%=;\n\t"
        "bra.uni WL_%=;\n\t"
        "WD_%=:\n\t"
        "}" :: "r"(mbar), "r"(parity) : "memory");
}

// ---------------------------------------------------------------------------
// Denominator: cluster of 2 CTAs per batch element. 256 threads each.
// ---------------------------------------------------------------------------
__device__ void den_block(unsigned char* smem_raw,
                          const float* __restrict__ logp,
                          const int* __restrict__ in_len_raw,
                          const float* __restrict__ trans,
                          const float* __restrict__ start,
                          int b, int h, int T, int U) {
    int tid = threadIdx.x;
    int g   = tid >> 7;       // 0: own-half producer (off-path); 1: critical path
    int j   = tid & 127;      // column within my half
    int gcol = h * 128 + j;   // global output column

    unsigned int sbase;
    asm("{ .reg .u64 t; cvta.to.shared.u64 t, %1; cvt.u32.u64 %0, t; }"
        : "=r"(sbase) : "l"(smem_raw));
    unsigned int mbar_l  = sbase + OFF_MBAR;
    unsigned int smbar_l = sbase + OFF_SMBAR;

    float* a_sh   = (float*)(smem_raw + OFF_ASH);
    float* p_in   = (float*)(smem_raw + OFF_PIN);
    float* part   = (float*)(smem_raw + OFF_PART);
    float* red    = (float*)(smem_raw + OFF_RED);
    float* tmp    = (float*)(smem_raw + OFF_TMP);
    float* s_slot = (float*)(smem_raw + OFF_SSLOT);

    int peer = h ^ 1;
    unsigned int mbar_p, smbar_p, pin_p, sslot_p;
    asm("mapa.shared::cluster.u32 %0, %1, %2;" : "=r"(mbar_p)  : "r"(mbar_l), "r"(peer));
    asm("mapa.shared::cluster.u32 %0, %1, %2;" : "=r"(smbar_p) : "r"(smbar_l), "r"(peer));
    asm("mapa.shared::cluster.u32 %0, %1, %2;" : "=r"(pin_p)   : "r"(sbase + OFF_PIN), "r"(peer));
    asm("mapa.shared::cluster.u32 %0, %1, %2;" : "=r"(sslot_p) : "r"(sbase + OFF_SSLOT), "r"(peer));

    if (tid == 0) {
        asm volatile("mbarrier.init.shared.b64 [%0], %1;" :: "r"(mbar_l),      "r"(1) : "memory");
        asm volatile("mbarrier.init.shared.b64 [%0], %1;" :: "r"(mbar_l + 8),  "r"(1) : "memory");
        asm volatile("mbarrier.init.shared.b64 [%0], %1;" :: "r"(smbar_l),     "r"(1) : "memory");
        asm volatile("mbarrier.init.shared.b64 [%0], %1;" :: "r"(smbar_l + 8), "r"(1) : "memory");
    }

    // T column slice in registers: rows [(h^g)*128, +128) for column gcol.
    unsigned long long Treg[64];
    const float* trow = trans + (size_t)((h ^ g) * 128) * CC + gcol;
#pragma unroll
    for (int rp = 0; rp < 64; rp++) {
        float e0 = __expf(trow[(2 * rp) * CC]);
        float e1 = __expf(trow[(2 * rp + 1) * CC]);
        Treg[rp] = pack2(e0, e1);
    }

    int inlen = in_len_raw[b];
    int lowc = 2 * U + 1;
    if (inlen < lowc) inlen = lowc;
    if (inlen > T)    inlen = T;

    const float* lpb = logp + (size_t)b * T * CC;

    // alpha0 = exp(start + logp[:,0]) normalized; seed a_sh (my half) and
    // p_in[0] (peer half, computed locally -- no exchange needed for t=1).
    float a0 = __expf(start[tid] + lpb[tid]);
    tmp[tid] = a0;
    __syncthreads();
    float s0 = blk_sum_256(a0, red);
    float logZ = logf(s0);
    float inv0 = 1.0f / s0;
    if (tid < 128) {
        a_sh[tid]     = tmp[h * 128 + tid] * inv0;
        p_in[0 + tid] = tmp[peer * 128 + tid] * inv0;
    }
    __syncthreads();

    asm volatile("barrier.cluster.arrive.aligned;" ::: "memory");
    asm volatile("barrier.cluster.wait.aligned;" ::: "memory");

    if (g == 0) {
        // --------------- g0: own-half dot producer (off-path) ---------------
        const longlong2* own2 = (const longlong2*)a_sh;
        for (int t = 1; t < inlen; ++t) {
            int buf = t & 1;
            if (tid == 0) {   // arm for incoming peer an(t): 128 floats
                asm volatile("mbarrier.arrive.expect_tx.shared.b64 _, [%0], %1;"
                             :: "r"(mbar_l + (unsigned)buf * 8u), "r"(512) : "memory");
            }
            unsigned long long acc0 = 0ull, acc1 = 0ull, acc2 = 0ull, acc3 = 0ull;
#pragma unroll
            for (int i = 0; i < 16; i++) {
                longlong2 x = own2[2 * i];
                longlong2 y = own2[2 * i + 1];
                asm("fma.rn.f32x2 %0, %1, %2, %0;" : "+l"(acc0) : "l"((unsigned long long)x.x), "l"(Treg[4 * i + 0]));
                asm("fma.rn.f32x2 %0, %1, %2, %0;" : "+l"(acc1) : "l"((unsigned long long)x.y), "l"(Treg[4 * i + 1]));
                asm("fma.rn.f32x2 %0, %1, %2, %0;" : "+l"(acc2) : "l"((unsigned long long)y.x), "l"(Treg[4 * i + 2]));
                asm("fma.rn.f32x2 %0, %1, %2, %0;" : "+l"(acc3) : "l"((unsigned long long)y.y), "l"(Treg[4 * i + 3]));
            }
            asm("add.rn.f32x2 %0, %0, %1;" : "+l"(acc0) : "l"(acc1));
            asm("add.rn.f32x2 %0, %0, %1;" : "+l"(acc2) : "l"(acc3));
            asm("add.rn.f32x2 %0, %0, %1;" : "+l"(acc0) : "l"(acc2));
            unsigned int plo, phi;
            asm("mov.b64 {%0, %1}, %2;" : "=r"(plo), "=r"(phi) : "l"(acc0));
            part[buf * 128 + j] = __uint_as_float(plo) + __uint_as_float(phi);

            asm volatile("bar.arrive 2, 256;" ::: "memory");   // part[buf] ready -> g1
            asm volatile("bar.sync 3, 256;"   ::: "memory");   // wait g1: a_sh = an(t)
        }
    } else {
        // --------------- g1: critical path (wait, FMA, combine, send) -------
        int ph0 = 0, ph1 = 0;   // per-buffer mbar phase parity
        int rc = 0;             // renorm counter
        float lp_reg = lpb[CC + gcol];   // frame t=1 for my column
        for (int t = 1; t < inlen; ++t) {
            int buf = t & 1;
            int br  = (t - 1) & 1;
            float pv = __expf(lp_reg);
            if (t + 1 < inlen) lp_reg = lpb[(size_t)(t + 1) * CC + gcol];

            if (t >= 2) {
                int par = br ? ph1 : ph0;
                mbar_wait_parity(mbar_l + (unsigned)br * 8u, (unsigned)par);
                if (br) ph1 ^= 1; else ph0 ^= 1;
            }
            const longlong2* src2 = (const longlong2*)(p_in + br * 128);
            unsigned long long acc0 = 0ull, acc1 = 0ull, acc2 = 0ull, acc3 = 0ull;
#pragma unroll
            for (int i = 0; i < 16; i++) {
                longlong2 x = src2[2 * i];
                longlong2 y = src2[2 * i + 1];
                asm("fma.rn.f32x2 %0, %1, %2, %0;" : "+l"(acc0) : "l"((unsigned long long)x.x), "l"(Treg[4 * i + 0]));
                asm("fma.rn.f32x2 %0, %1, %2, %0;" : "+l"(acc1) : "l"((unsigned long long)x.y), "l"(Treg[4 * i + 1]));
                asm("fma.rn.f32x2 %0, %1, %2, %0;" : "+l"(acc2) : "l"((unsigned long long)y.x), "l"(Treg[4 * i + 2]));
                asm("fma.rn.f32x2 %0, %1, %2, %0;" : "+l"(acc3) : "l"((unsigned long long)y.y), "l"(Treg[4 * i + 3]));
            }
            asm("add.rn.f32x2 %0, %0, %1;" : "+l"(acc0) : "l"(acc1));
            asm("add.rn.f32x2 %0, %0, %1;" : "+l"(acc2) : "l"(acc3));
            asm("add.rn.f32x2 %0, %0, %1;" : "+l"(acc0) : "l"(acc2));
            unsigned int plo, phi;
            asm("mov.b64 {%0, %1}, %2;" : "=r"(plo), "=r"(phi) : "l"(acc0));
            float peer_dot = __uint_as_float(plo) + __uint_as_float(phi);

            asm volatile("bar.sync 2, 256;" ::: "memory");     // g0's part[buf] ready
            float an = (part[buf * 128 + j] + peer_dot) * pv;

            if (((t & 31) == 31) || (t == inlen - 1)) {
                // g1-only renorm (warps 4-7)
                float v = an;
#pragma unroll
                for (int o = 16; o > 0; o >>= 1) v += __shfl_xor_sync(0xffffffffu, v, o);
                if ((tid & 31) == 0) red[(tid >> 5) - 4] = v;
                asm volatile("bar.sync 4, 128;" ::: "memory");
                float sl = red[0] + red[1] + red[2] + red[3];
                int bs = rc & 1;
                if (tid == 128) {
                    asm volatile("mbarrier.arrive.expect_tx.shared.b64 _, [%0], %1;"
                                 :: "r"(smbar_l + (unsigned)bs * 8u), "r"(4) : "memory");
                    asm volatile("st.async.shared::cluster.mbarrier::complete_tx::bytes.b32"
                                 " [%0], %1, [%2];"
                                 :: "r"(sslot_p + (unsigned)bs * 4u),
                                    "r"(__float_as_uint(sl)),
                                    "r"(smbar_p + (unsigned)bs * 8u) : "memory");
                }
                mbar_wait_parity(smbar_l + (unsigned)bs * 8u, (unsigned)((rc >> 1) & 1));
                float sp = s_slot[bs];
                float s  = (h == 0) ? (sl + sp) : (sp + sl);   // CTA0 half first
                logZ += logf(s);
                an *= (1.0f / s);
                rc++;
                asm volatile("bar.sync 4, 128;" ::: "memory"); // red WAR
            }

            a_sh[j] = an;   // for g0's own-dot next step
            asm volatile("st.async.shared::cluster.mbarrier::complete_tx::bytes.b32"
                         " [%0], %1, [%2];"
                         :: "r"(pin_p + (unsigned)buf * 512u + (unsigned)j * 4u),
                            "r"(__float_as_uint(an)),
                            "r"(mbar_p + (unsigned)buf * 8u) : "memory");
            asm volatile("bar.arrive 3, 256;" ::: "memory");   // release g0
        }
        if (h == 0 && tid == 128) g_den[b] = logZ;
    }

    asm volatile("barrier.cluster.arrive.aligned;" ::: "memory");
    asm volatile("barrier.cluster.wait.aligned;" ::: "memory");
}

// ---------------------------------------------------------------------------
// CTC numerator block (LOG domain): one block per batch element. 256 threads.
// ---------------------------------------------------------------------------
__device__ void ctc_block(unsigned char* smem_raw,
                          const float* __restrict__ logp,
                          const int* __restrict__ targets,
                          const int* __restrict__ in_len_raw,
                          const int* __restrict__ tgt_len_raw,
                          int b, int T, int U) {
    int tid = threadIdx.x;
    int S = 2 * U + 1;

    float* A0  = (float*)smem_raw;          // S+6 (2 leading NEG guards)
    float* A1  = A0 + (S + 6);
    int*   lab = (int*)(A1 + (S + 6));      // S
    int*   skp = lab + S;                   // S
    float* pc  = (float*)(skp + S);         // 256

    const int* tg = targets + (size_t)b * U;
    int tlen = tgt_len_raw[b];
    if (tlen < 1) tlen = 1;
    if (tlen > U) tlen = U;
    int inlen = in_len_raw[b];
    int lowc = 2 * U + 1;
    if (inlen < lowc) inlen = lowc;
    if (inlen > T)    inlen = T;

    for (int s = tid; s < S; s += 256) {
        int l = 0;
        if (s & 1) {
            l = tg[s >> 1];
            if (l < 1) l = 1;
            if (l > CC - 1) l = CC - 1;
        }
        lab[s] = l;
    }
    for (int s = tid; s < S + 6; s += 256) { A0[s] = NEGBIG; A1[s] = NEGBIG; }
    __syncthreads();
    for (int s = tid; s < S; s += 256)
        skp[s] = (s >= 2 && (s & 1) && lab[s] != lab[s - 2]) ? 1 : 0;

    const float* lpb = logp + (size_t)b * T * CC;
    if (tid == 0) {
        A0[2 + 0] = lpb[0];
        A0[2 + 1] = lpb[lab[1]];
    }
    pc[tid] = lpb[CC + tid];
    float lp_reg = lpb[2 * (size_t)CC + tid];
    __syncthreads();

    float* cur = A0;
    float* nxt = A1;
    for (int t = 1; t < inlen; ++t) {
        {
            int s = tid;
            float a  = cur[s + 2];
            float a1 = cur[s + 1];
            float a2 = skp[s] ? cur[s] : NEGBIG;
            float m  = fmaxf(fmaxf(a, a1), a2);
            float v  = __expf(a - m) + __expf(a1 - m) + __expf(a2 - m);
            nxt[s + 2] = m + __logf(v) + pc[lab[s]];
        }
        if (tid < S - 256) {
            int s = tid + 256;
            float a  = cur[s + 2];
            float a1 = cur[s + 1];
            float a2 = skp[s] ? cur[s] : NEGBIG;
            float m  = fmaxf(fmaxf(a, a1), a2);
            float v  = __expf(a - m) + __expf(a1 - m) + __expf(a2 - m);
            nxt[s + 2] = m + __logf(v) + pc[lab[s]];
        }
        __syncthreads();
        if (t + 1 < inlen) {
            pc[tid] = lp_reg;
            if (t + 2 < inlen) lp_reg = lpb[(size_t)(t + 2) * CC + tid];
        }
        __syncthreads();
        float* tmp = cur; cur = nxt; nxt = tmp;
    }
    if (tid == 0) {
        int last = 2 * tlen;
        float a  = cur[last + 2];
        float a1 = cur[last + 1];
        float m  = fmaxf(a, a1);
        g_num[b] = m + logf(expf(a - m) + expf(a1 - m));
    }
}

__global__ __launch_bounds__(256, 1) __cluster_dims__(2, 1, 1)
void lfmmi_kernel(const float* __restrict__ logp,
                  const int* __restrict__ targets,
                  const int* __restrict__ in_len_raw,
                  const int* __restrict__ tgt_len_raw,
                  const float* __restrict__ trans,
                  const float* __restrict__ start,
                  float* __restrict__ out,
                  int B, int T, int U) {
    extern __shared__ unsigned char smem_raw[];
    int blk = blockIdx.x;
    if (blk < 2 * B) {
        den_block(smem_raw, logp, in_len_raw, trans, start, blk >> 1, blk & 1, T, U);
    } else if (blk < 3 * B) {
        ctc_block(smem_raw, logp, targets, in_len_raw, tgt_len_raw, blk - 2 * B, T, U);
    }

    // ---- fused finalize: last block to finish reduces g_num/g_den -> out ----
    __syncthreads();
    if (threadIdx.x == 0) {
        __threadfence();
        unsigned int total = gridDim.x;
        unsigned int old = atomicAdd(&g_done, 1u);
        if ((old % total) == total - 1u) {
            __threadfence();
            float tot = 0.f;
            int cnt = 0;
            for (int b = 0; b < B; b++) {
                float v = g_num[b] - g_den[b];
                if (v > 0.5f * NEGBIG) { tot += v; cnt++; }
            }
            int n = (cnt > 0) ? cnt : 1;
            out[0] = -tot / (float)n;
        }
    }
}

extern "C" void kernel_launch(void* const* d_in, const int* in_sizes, int n_in,
                              void* d_out, int out_size) {
    const float* logp   = (const float*)d_in[0];
    const int*   tgts   = (const int*)d_in[1];
    const int*   inl    = (const int*)d_in[2];
    const int*   tgl    = (const int*)d_in[3];
    const float* trans  = (const float*)d_in[4];
    const float* start  = (const float*)d_in[5];

    int B = in_sizes[2];
    int C = in_sizes[5];            // expected 256
    int U = in_sizes[1] / B;
    int T = in_sizes[0] / (B * C);
    int S = 2 * U + 1;

    size_t ctc_smem = (size_t)(2 * (S + 6) + 2 * S + 256 + 16) * 4;
    size_t smem = ctc_smem > DEN_SMEM ? ctc_smem : DEN_SMEM;

    int grid = 3 * B;
    if (grid & 1) grid++;           // cluster size 2 divisibility

    lfmmi_kernel<<<grid, 256, smem>>>(logp, tgts, inl, tgl, trans, start,
                                      (float*)d_out, B, T, U);
}